// round 2
// baseline (speedup 1.0000x reference)
#include <cuda_runtime.h>
#include <float.h>
#include <math.h>

// Problem shape (fixed by the dataset): B=4096, M=8192, K=32 neighbors.
#define BMAX  4096
#define TPB   256
#define NW    8          // warps per block
#define CHUNK 512        // elements per warp (BMAX / NW)
#define SEG   16         // elements per lane within a warp chunk
#define KNB   32         // neighbors
#define KSEL  33         // extract top-33 (33rd = max over mask==0)
#define CPW   36         // padded candidate slots per warp
#define MDEEP 9          // (NW*CPW)/32 = 288/32 candidates per merge lane

__device__ float g_centrality[BMAX];
__device__ float g_rowloss[BMAX];

// Orderable-float keys: monotone bijection float -> u32 (for integer redux).
__device__ __forceinline__ unsigned okey(float v) {
    unsigned u = __float_as_uint(v);
    return (u & 0x80000000u) ? ~u : (u | 0x80000000u);
}
__device__ __forceinline__ float unkey(unsigned k) {
    unsigned u = (k & 0x80000000u) ? (k & 0x7fffffffu) : ~k;
    return __uint_as_float(u);
}

// ---------------------------------------------------------------------------
// Kernel 1: centrality[row] = mean(memory_bank[row, :])
// ---------------------------------------------------------------------------
__global__ __launch_bounds__(TPB) void centrality_kernel(
    const float* __restrict__ mem, int B, int M)
{
    int row = blockIdx.x;
    const float4* p = (const float4*)(mem + (size_t)row * M);
    int n4 = M >> 2;
    float s0 = 0.f, s1 = 0.f;
    int j = threadIdx.x;
    for (; j + TPB < n4; j += 2 * TPB) {
        float4 a = p[j];
        float4 b = p[j + TPB];
        s0 += (a.x + a.y) + (a.z + a.w);
        s1 += (b.x + b.y) + (b.z + b.w);
    }
    for (; j < n4; j += TPB) {
        float4 a = p[j];
        s0 += (a.x + a.y) + (a.z + a.w);
    }
    float s = s0 + s1;
    __shared__ float ws[TPB / 32];
    #pragma unroll
    for (int o = 16; o > 0; o >>= 1) s += __shfl_down_sync(0xffffffffu, s, o);
    if ((threadIdx.x & 31) == 0) ws[threadIdx.x >> 5] = s;
    __syncthreads();
    if (threadIdx.x < 32) {
        float t = (threadIdx.x < TPB / 32) ? ws[threadIdx.x] : 0.f;
        #pragma unroll
        for (int o = 4; o > 0; o >>= 1) t += __shfl_down_sync(0xffffffffu, t, o);
        if (threadIdx.x == 0) g_centrality[row] = t / (float)M;
    }
}

// ---------------------------------------------------------------------------
// Kernel 2: per-row loss. One CTA (256 threads = 8 warps) per row.
// ---------------------------------------------------------------------------
__global__ __launch_bounds__(TPB) void rowloss_kernel(
    const float* __restrict__ sim, const float* __restrict__ temp_p, int B)
{
    __shared__ float    srow[BMAX];
    __shared__ float    cand_val[NW * CPW];
    __shared__ int      cand_idx[NW * CPW];
    __shared__ unsigned bitmap[BMAX / 32];
    __shared__ float    topval[KSEL];
    __shared__ int      topidx[KSEL];
    __shared__ unsigned wminkey[NW];
    __shared__ unsigned ckeys[2 * NW];
    __shared__ float    sh_diag;
    __shared__ float    sh_sc[4];   // mn_s, mx_s, mn_c, mx_c

    const int i    = blockIdx.x;
    const int tid  = threadIdx.x;
    const int wid  = tid >> 5;
    const int lane = tid & 31;
    const float NEG = -FLT_MAX;

    // ---- load row, zero bitmap ----
    const float4* rp = (const float4*)(sim + (size_t)i * B);
    for (int j = tid; j < (B >> 2); j += TPB) ((float4*)srow)[j] = rp[j];
    for (int j = tid; j < (B >> 5); j += TPB) bitmap[j] = 0u;
    __syncthreads();
    if (tid == 0) {
        sh_diag = srow[i];
        srow[i] = NEG;                       // exclude diagonal from selection
        bitmap[i >> 5] |= 1u << (i & 31);
    }
    __syncthreads();

    // ---- warp phase: each warp extracts top-33 of its 512-chunk (no barriers).
    //      Also computes chunk min (excludes only the diag sentinel; the removed
    //      maxima can never be the min, so this equals min over mask==0). ----
    {
        const int base = wid * CHUNK + lane * SEG;
        unsigned best = 0u; int argi = base;
        unsigned mink = 0xffffffffu;
        #pragma unroll
        for (int j = 0; j < SEG; j++) {
            float v = srow[base + j];
            unsigned k = okey(v);
            if (k > best) { best = k; argi = base + j; }
            if (v != NEG) mink = min(mink, k);
        }
        mink = __reduce_min_sync(0xffffffffu, mink);
        if (lane == 0) wminkey[wid] = mink;

        for (int k = 0; k < KSEL; k++) {
            unsigned m    = __reduce_max_sync(0xffffffffu, best);
            unsigned ball = __ballot_sync(0xffffffffu, best == m);
            if (lane == (__ffs(ball) - 1)) {
                cand_val[wid * CPW + k] = srow[argi];
                cand_idx[wid * CPW + k] = argi;
                srow[argi] = NEG;
                best = 0u; argi = base;
                #pragma unroll
                for (int j = 0; j < SEG; j++) {
                    unsigned kk = okey(srow[base + j]);
                    if (kk > best) { best = kk; argi = base + j; }
                }
            }
        }
        if (lane < CPW - KSEL) {             // pad slots 33..35
            cand_val[wid * CPW + KSEL + lane] = NEG;
            cand_idx[wid * CPW + KSEL + lane] = 0;
        }
    }
    __syncthreads();

    // ---- merge (warp 0): global top-33 of 288 candidates. Winners 0..31 are
    //      the neighbors (bitmap bits set); winner 32's value = mx_s. ----
    if (wid == 0) {
        const int base = lane * MDEEP;
        unsigned best = 0u; int argc = base;
        #pragma unroll
        for (int j = 0; j < MDEEP; j++) {
            unsigned kk = okey(cand_val[base + j]);
            if (kk > best) { best = kk; argc = base + j; }
        }
        for (int k = 0; k < KSEL; k++) {
            unsigned m    = __reduce_max_sync(0xffffffffu, best);
            unsigned ball = __ballot_sync(0xffffffffu, best == m);
            if (lane == (__ffs(ball) - 1)) {
                topval[k] = cand_val[argc];
                int gi = cand_idx[argc];
                topidx[k] = gi;
                if (k < KNB) bitmap[gi >> 5] |= 1u << (gi & 31);
                cand_val[argc] = NEG;
                best = 0u; argc = base;
                #pragma unroll
                for (int j = 0; j < MDEEP; j++) {
                    unsigned kk = okey(cand_val[base + j]);
                    if (kk > best) { best = kk; argc = base + j; }
                }
            }
        }
    }
    __syncthreads();

    // ---- centrality min/max over non-excluded (bitmap has diag + 32 bits) ----
    {
        unsigned cmin = 0xffffffffu, cmax = 0u;
        const int base = tid * SEG;
        #pragma unroll
        for (int j = 0; j < SEG; j++) {
            int idx = base + j;
            if (!((bitmap[idx >> 5] >> (idx & 31)) & 1u)) {
                unsigned k = okey(g_centrality[idx]);
                cmin = min(cmin, k);
                cmax = max(cmax, k);
            }
        }
        cmin = __reduce_min_sync(0xffffffffu, cmin);
        cmax = __reduce_max_sync(0xffffffffu, cmax);
        if (lane == 0) { ckeys[wid] = cmin; ckeys[NW + wid] = cmax; }
    }
    __syncthreads();
    if (tid == 0) {
        unsigned a = 0xffffffffu, b = 0u, c = 0xffffffffu;
        #pragma unroll
        for (int w = 0; w < NW; w++) {
            a = min(a, ckeys[w]);
            b = max(b, ckeys[NW + w]);
            c = min(c, wminkey[w]);
        }
        sh_sc[0] = unkey(c);       // mn_s
        sh_sc[1] = topval[KNB];    // mx_s = 33rd largest off-diag
        sh_sc[2] = unkey(a);       // mn_c
        sh_sc[3] = unkey(b);       // mx_c
    }
    __syncthreads();

    // ---- epilogue: warp 0, one lane per neighbor ----
    if (tid < 32) {
        float mn_s = sh_sc[0], mx_s = sh_sc[1], mn_c = sh_sc[2], mx_c = sh_sc[3];
        float tv = topval[tid];
        int   ti = topidx[tid];
        float dg = sh_diag;

        // logsumexp over extended set (32 neighbors + diagonal)
        float m = tv;
        #pragma unroll
        for (int o = 16; o > 0; o >>= 1) m = fmaxf(m, __shfl_xor_sync(0xffffffffu, m, o));
        m = fmaxf(m, dg);
        float s = expf(tv - m);
        #pragma unroll
        for (int o = 16; o > 0; o >>= 1) s += __shfl_xor_sync(0xffffffffu, s, o);
        s += expf(dg - m);
        float lse = logf(s) + m;

        // positive weights: softmax over 32 neighbors of (norm_sim - norm_cent)*T
        float T  = *temp_p;
        float ns = (tv - mn_s) / (mx_s - mn_s);
        float nc = (g_centrality[ti] - mn_c) / (mx_c - mn_c);
        float a  = (ns - nc) * T;
        float am = a;
        #pragma unroll
        for (int o = 16; o > 0; o >>= 1) am = fmaxf(am, __shfl_xor_sync(0xffffffffu, am, o));
        float pe = expf(a - am);
        float ps = pe;
        #pragma unroll
        for (int o = 16; o > 0; o >>= 1) ps += __shfl_xor_sync(0xffffffffu, ps, o);
        float pw = pe / ps;

        float num   = pw * (tv - lse);
        float pwsum = pw;
        #pragma unroll
        for (int o = 16; o > 0; o >>= 1) {
            num   += __shfl_xor_sync(0xffffffffu, num,   o);
            pwsum += __shfl_xor_sync(0xffffffffu, pwsum, o);
        }
        if (tid == 0) {
            float numer = num + (dg - lse);
            float denom = pwsum + 1.0f;
            g_rowloss[i] = -numer / denom;
        }
    }
}

// ---------------------------------------------------------------------------
// Kernel 3: deterministic mean over rows
// ---------------------------------------------------------------------------
__global__ __launch_bounds__(TPB) void reduce_kernel(float* __restrict__ out, int B)
{
    double s = 0.0;
    for (int j = threadIdx.x; j < B; j += TPB) s += (double)g_rowloss[j];
    __shared__ double ws[TPB / 32];
    #pragma unroll
    for (int o = 16; o > 0; o >>= 1) s += __shfl_down_sync(0xffffffffu, s, o);
    if ((threadIdx.x & 31) == 0) ws[threadIdx.x >> 5] = s;
    __syncthreads();
    if (threadIdx.x < 32) {
        double t = (threadIdx.x < TPB / 32) ? ws[threadIdx.x] : 0.0;
        #pragma unroll
        for (int o = 4; o > 0; o >>= 1) t += __shfl_down_sync(0xffffffffu, t, o);
        if (threadIdx.x == 0) out[0] = (float)(t / (double)B);
    }
}

// ---------------------------------------------------------------------------
extern "C" void kernel_launch(void* const* d_in, const int* in_sizes, int n_in,
                              void* d_out, int out_size)
{
    const float* sim  = (const float*)d_in[0];
    const float* mem  = (const float*)d_in[1];
    const float* temp = (const float*)d_in[n_in - 1];

    int nsim = in_sizes[0];
    int B = 1;
    while ((long long)B * B < (long long)nsim) B <<= 1;   // B = 4096
    int M = in_sizes[1] / B;                               // M = 8192

    centrality_kernel<<<B, TPB>>>(mem, B, M);
    rowloss_kernel<<<B, TPB>>>(sim, temp, B);
    reduce_kernel<<<1, TPB>>>((float*)d_out, B);
}

// round 4
// speedup vs baseline: 3.3156x; 3.3156x over previous
#include <cuda_runtime.h>
#include <float.h>
#include <math.h>

// Problem shape (fixed by dataset): B=4096, M=8192, K=32 neighbors.
#define BMAX  4096
#define TPB   256
#define NW    8
#define SEG   16          // BMAX / TPB
#define KNB   32
#define NBINS 256
#define CAP   512         // candidate capacity (expected ~36)

__device__ float g_centrality[BMAX];
__device__ float g_rowloss[BMAX];

__device__ __forceinline__ unsigned okey(float v) {
    unsigned u = __float_as_uint(v);
    return (u & 0x80000000u) ? ~u : (u | 0x80000000u);
}
__device__ __forceinline__ float unkey(unsigned k) {
    unsigned u = (k & 0x80000000u) ? (k & 0x7fffffffu) : ~k;
    return __uint_as_float(u);
}

// ---------------------------------------------------------------------------
// Kernel 1: centrality[row] = mean(memory_bank[row, :])
// ---------------------------------------------------------------------------
__global__ __launch_bounds__(TPB) void centrality_kernel(
    const float* __restrict__ mem, int B, int M)
{
    int row = blockIdx.x;
    const float4* p = (const float4*)(mem + (size_t)row * M);
    int n4 = M >> 2;                       // 2048
    float s0 = 0.f, s1 = 0.f, s2 = 0.f, s3 = 0.f;
    int j = threadIdx.x;
    for (; j + 3 * TPB < n4; j += 4 * TPB) {
        float4 a = p[j];
        float4 b = p[j + TPB];
        float4 c = p[j + 2 * TPB];
        float4 d = p[j + 3 * TPB];
        s0 += (a.x + a.y) + (a.z + a.w);
        s1 += (b.x + b.y) + (b.z + b.w);
        s2 += (c.x + c.y) + (c.z + c.w);
        s3 += (d.x + d.y) + (d.z + d.w);
    }
    for (; j < n4; j += TPB) {
        float4 a = p[j];
        s0 += (a.x + a.y) + (a.z + a.w);
    }
    float s = (s0 + s1) + (s2 + s3);
    __shared__ float ws[NW];
    #pragma unroll
    for (int o = 16; o > 0; o >>= 1) s += __shfl_down_sync(0xffffffffu, s, o);
    if ((threadIdx.x & 31) == 0) ws[threadIdx.x >> 5] = s;
    __syncthreads();
    if (threadIdx.x < 32) {
        float t = (threadIdx.x < NW) ? ws[threadIdx.x] : 0.f;
        #pragma unroll
        for (int o = 4; o > 0; o >>= 1) t += __shfl_down_sync(0xffffffffu, t, o);
        if (threadIdx.x == 0) g_centrality[row] = t / (float)M;
    }
}

// ---------------------------------------------------------------------------
// Kernel 2: per-row loss via histogram-select (no iterative tournaments).
// ---------------------------------------------------------------------------
__global__ __launch_bounds__(TPB) void rowloss_kernel(
    const float* __restrict__ sim, const float* __restrict__ temp_p, int B)
{
    __shared__ float    srow[BMAX];
    __shared__ unsigned hist[NBINS];
    __shared__ unsigned bitmap[BMAX / 32];
    __shared__ float    cand_val[CAP];
    __shared__ int      cand_idx[CAP];
    __shared__ float    topval[KNB];
    __shared__ int      topidx[KNB];
    __shared__ float    wmn[NW], wmx[NW];
    __shared__ unsigned ckeys[2 * NW];
    __shared__ unsigned sh_cnt;
    __shared__ int      sh_bstar;
    __shared__ float    sh_lo, sh_scale, sh_diag;
    __shared__ float    sh_sc[4];        // mn_s, mx_s, mn_c, mx_c

    const int i    = blockIdx.x;
    const int tid  = threadIdx.x;
    const int wid  = tid >> 5;
    const int lane = tid & 31;

    // ---- load row (gmem -> smem), off-diag min/max on the fly; zero aux ----
    float mn = FLT_MAX, mx = -FLT_MAX;
    {
        const float4* rp = (const float4*)(sim + (size_t)i * B);
        const int dq = i >> 2, dl = i & 3;         // diag's float4 / lane-in-4
        #pragma unroll
        for (int k = 0; k < 4; k++) {
            int j = tid + k * TPB;                  // 1024 float4s total
            float4 v = rp[j];
            ((float4*)srow)[j] = v;
            float a = v.x, b = v.y, c = v.z, d = v.w;
            if (j == dq) {                          // exclude diagonal
                float dv = (dl == 0) ? a : (dl == 1) ? b : (dl == 2) ? c : d;
                sh_diag = dv;
                const float rep = (dl == 0) ? b : a;   // neutral replacement
                if (dl == 0) a = rep; else if (dl == 1) b = rep;
                else if (dl == 2) c = rep; else d = rep;
            }
            mn = fminf(mn, fminf(fminf(a, b), fminf(c, d)));
            mx = fmaxf(mx, fmaxf(fmaxf(a, b), fmaxf(c, d)));
        }
        if (tid < NBINS) hist[tid] = 0u;
        if (tid < (BMAX >> 5)) bitmap[tid] = 0u;
        if (tid == 0) sh_cnt = 0u;
    }
    #pragma unroll
    for (int o = 16; o > 0; o >>= 1) {
        mn = fminf(mn, __shfl_xor_sync(0xffffffffu, mn, o));
        mx = fmaxf(mx, __shfl_xor_sync(0xffffffffu, mx, o));
    }
    if (lane == 0) { wmn[wid] = mn; wmx[wid] = mx; }
    __syncthreads();
    if (tid == 0) {
        float lo = wmn[0], hi = wmx[0];
        #pragma unroll
        for (int w = 1; w < NW; w++) { lo = fminf(lo, wmn[w]); hi = fmaxf(hi, wmx[w]); }
        sh_lo = lo;
        sh_scale = (float)NBINS / fmaxf(hi - lo, 1e-30f);
        bitmap[i >> 5] |= 1u << (i & 31);          // diag bit (after zeroing)
    }
    __syncthreads();

    const float lo = sh_lo, scale = sh_scale;

    // ---- histogram pass (shared atomics; skip diagonal) ----
    #pragma unroll
    for (int k = 0; k < 4; k++) {
        int j = tid + k * TPB;
        float4 v = ((const float4*)srow)[j];
        int base = j << 2;
        #pragma unroll
        for (int e = 0; e < 4; e++) {
            float f = (e == 0) ? v.x : (e == 1) ? v.y : (e == 2) ? v.z : v.w;
            int idx = base + e;
            if (idx != i) {
                int b = (int)((f - lo) * scale);
                b = min(max(b, 0), NBINS - 1);
                atomicAdd(&hist[b], 1u);
            }
        }
    }
    __syncthreads();

    // ---- find boundary bin b*: largest b with cum-from-top(b) >= 33 ----
    if (wid == 0) {
        unsigned running = 0u;
        int bstar = 0;
        bool found = false;
        for (int c = 0; c < NBINS / 32 && !found; c++) {
            int bin = NBINS - 1 - c * 32 - lane;
            unsigned p = hist[bin];
            #pragma unroll
            for (int o = 1; o < 32; o <<= 1) {
                unsigned t = __shfl_up_sync(0xffffffffu, p, o);
                if (lane >= o) p += t;
            }
            unsigned cum = running + p;
            unsigned ball = __ballot_sync(0xffffffffu, cum >= 33u);
            running += __shfl_sync(0xffffffffu, p, 31);
            if (ball) { bstar = NBINS - 1 - c * 32 - (__ffs(ball) - 1); found = true; }
        }
        if (lane == 0) sh_bstar = bstar;
    }
    __syncthreads();

    // ---- collect candidates with bin >= b* (expected ~36) ----
    {
        const int bstar = sh_bstar;
        #pragma unroll
        for (int k = 0; k < 4; k++) {
            int j = tid + k * TPB;
            float4 v = ((const float4*)srow)[j];
            int base = j << 2;
            #pragma unroll
            for (int e = 0; e < 4; e++) {
                float f = (e == 0) ? v.x : (e == 1) ? v.y : (e == 2) ? v.z : v.w;
                int idx = base + e;
                if (idx != i) {
                    int b = (int)((f - lo) * scale);
                    b = min(max(b, 0), NBINS - 1);
                    if (b >= bstar) {
                        unsigned pos = atomicAdd(&sh_cnt, 1u);
                        if (pos < CAP) { cand_val[pos] = f; cand_idx[pos] = idx; }
                    }
                }
            }
        }
    }
    __syncthreads();

    // ---- exact rank by counting (ties: lower index wins, matches top_k) ----
    {
        int n = (int)min(sh_cnt, (unsigned)CAP);
        for (int c = tid; c < n; c += TPB) {
            float v = cand_val[c];
            int   id = cand_idx[c];
            int r = 0;
            for (int d = 0; d < n; d++) {
                float vd = cand_val[d];
                r += (vd > v) || (vd == v && cand_idx[d] < id);
            }
            if (r < KNB) {
                topval[r] = v;
                topidx[r] = id;
                atomicOr(&bitmap[id >> 5], 1u << (id & 31));
            } else if (r == KNB) {
                sh_sc[1] = v;                      // mx_s = 33rd largest off-diag
            }
        }
    }
    __syncthreads();

    // ---- centrality min/max over non-excluded positions ----
    {
        unsigned cmin = 0xffffffffu, cmax = 0u;
        #pragma unroll
        for (int k = 0; k < SEG; k++) {
            int idx = tid + k * TPB;
            if (!((bitmap[idx >> 5] >> (idx & 31)) & 1u)) {
                unsigned kk = okey(g_centrality[idx]);
                cmin = min(cmin, kk);
                cmax = max(cmax, kk);
            }
        }
        #pragma unroll
        for (int o = 16; o > 0; o >>= 1) {
            cmin = min(cmin, __shfl_xor_sync(0xffffffffu, cmin, o));
            cmax = max(cmax, __shfl_xor_sync(0xffffffffu, cmax, o));
        }
        if (lane == 0) { ckeys[wid] = cmin; ckeys[NW + wid] = cmax; }
    }
    __syncthreads();
    if (tid == 0) {
        unsigned a = 0xffffffffu, b = 0u;
        #pragma unroll
        for (int w = 0; w < NW; w++) { a = min(a, ckeys[w]); b = max(b, ckeys[NW + w]); }
        sh_sc[0] = sh_lo;          // mn_s = off-diag row min
        sh_sc[2] = unkey(a);       // mn_c
        sh_sc[3] = unkey(b);       // mx_c
    }
    __syncthreads();

    // ---- epilogue: warp 0, one lane per neighbor ----
    if (tid < 32) {
        float mn_s = sh_sc[0], mx_s = sh_sc[1], mn_c = sh_sc[2], mx_c = sh_sc[3];
        float tv = topval[tid];
        int   ti = topidx[tid];
        float dg = sh_diag;

        // logsumexp over extended set (32 neighbors + diagonal)
        float m = tv;
        #pragma unroll
        for (int o = 16; o > 0; o >>= 1) m = fmaxf(m, __shfl_xor_sync(0xffffffffu, m, o));
        m = fmaxf(m, dg);
        float s = expf(tv - m);
        #pragma unroll
        for (int o = 16; o > 0; o >>= 1) s += __shfl_xor_sync(0xffffffffu, s, o);
        s += expf(dg - m);
        float lse = logf(s) + m;

        // positive weights: softmax over neighbors of (norm_sim - norm_cent)*T
        float T  = *temp_p;
        float ns = (tv - mn_s) / (mx_s - mn_s);
        float nc = (g_centrality[ti] - mn_c) / (mx_c - mn_c);
        float a  = (ns - nc) * T;
        float am = a;
        #pragma unroll
        for (int o = 16; o > 0; o >>= 1) am = fmaxf(am, __shfl_xor_sync(0xffffffffu, am, o));
        float pe = expf(a - am);
        float ps = pe;
        #pragma unroll
        for (int o = 16; o > 0; o >>= 1) ps += __shfl_xor_sync(0xffffffffu, ps, o);
        float pw = pe / ps;

        float num   = pw * (tv - lse);
        float pwsum = pw;
        #pragma unroll
        for (int o = 16; o > 0; o >>= 1) {
            num   += __shfl_xor_sync(0xffffffffu, num,   o);
            pwsum += __shfl_xor_sync(0xffffffffu, pwsum, o);
        }
        if (tid == 0) {
            float numer = num + (dg - lse);
            float denom = pwsum + 1.0f;
            g_rowloss[i] = -numer / denom;
        }
    }
}

// ---------------------------------------------------------------------------
// Kernel 3: deterministic mean over rows
// ---------------------------------------------------------------------------
__global__ __launch_bounds__(TPB) void reduce_kernel(float* __restrict__ out, int B)
{
    double s = 0.0;
    for (int j = threadIdx.x; j < B; j += TPB) s += (double)g_rowloss[j];
    __shared__ double ws[NW];
    #pragma unroll
    for (int o = 16; o > 0; o >>= 1) s += __shfl_down_sync(0xffffffffu, s, o);
    if ((threadIdx.x & 31) == 0) ws[threadIdx.x >> 5] = s;
    __syncthreads();
    if (threadIdx.x < 32) {
        double t = (threadIdx.x < NW) ? ws[threadIdx.x] : 0.0;
        #pragma unroll
        for (int o = 4; o > 0; o >>= 1) t += __shfl_down_sync(0xffffffffu, t, o);
        if (threadIdx.x == 0) out[0] = (float)(t / (double)B);
    }
}

// ---------------------------------------------------------------------------
extern "C" void kernel_launch(void* const* d_in, const int* in_sizes, int n_in,
                              void* d_out, int out_size)
{
    const float* sim  = (const float*)d_in[0];
    const float* mem  = (const float*)d_in[1];
    const float* temp = (const float*)d_in[n_in - 1];

    int nsim = in_sizes[0];
    int B = 1;
    while ((long long)B * B < (long long)nsim) B <<= 1;   // B = 4096
    int M = in_sizes[1] / B;                               // M = 8192

    centrality_kernel<<<B, TPB>>>(mem, B, M);
    rowloss_kernel<<<B, TPB>>>(sim, temp, B);
    reduce_kernel<<<1, TPB>>>((float*)d_out, B);
}

// round 5
// speedup vs baseline: 3.6027x; 1.0866x over previous
#include <cuda_runtime.h>
#include <float.h>
#include <math.h>

// Problem shape (fixed by dataset): B=4096, M=8192, K=32 neighbors.
#define BMAX  4096
#define TPB   256
#define NW    8
#define KNB   32
#define NBINS 256
#define CAP   512         // candidate capacity (expected ~60)
#define NEXT  34          // centrality extremes kept per end
#define CECAP 256

__device__ float g_centrality[BMAX];
__device__ float g_rowloss[BMAX];
__device__ float g_topv[NEXT]; __device__ int g_topi[NEXT];   // centrality top-34 desc
__device__ float g_botv[NEXT]; __device__ int g_boti[NEXT];   // centrality bot-34 asc

// ---------------------------------------------------------------------------
// Kernel 1: centrality[row] = mean(memory_bank[row, :])
// ---------------------------------------------------------------------------
__global__ __launch_bounds__(TPB) void centrality_kernel(
    const float* __restrict__ mem, int B, int M)
{
    int row = blockIdx.x;
    const float4* p = (const float4*)(mem + (size_t)row * M);
    // M = 8192 -> 2048 float4 -> exactly 8 per thread; fully batched loads.
    float4 v0 = p[threadIdx.x + 0 * TPB];
    float4 v1 = p[threadIdx.x + 1 * TPB];
    float4 v2 = p[threadIdx.x + 2 * TPB];
    float4 v3 = p[threadIdx.x + 3 * TPB];
    float4 v4 = p[threadIdx.x + 4 * TPB];
    float4 v5 = p[threadIdx.x + 5 * TPB];
    float4 v6 = p[threadIdx.x + 6 * TPB];
    float4 v7 = p[threadIdx.x + 7 * TPB];
    float s = (((v0.x + v0.y) + (v0.z + v0.w)) + ((v1.x + v1.y) + (v1.z + v1.w)))
            + (((v2.x + v2.y) + (v2.z + v2.w)) + ((v3.x + v3.y) + (v3.z + v3.w)))
            + (((v4.x + v4.y) + (v4.z + v4.w)) + ((v5.x + v5.y) + (v5.z + v5.w)))
            + (((v6.x + v6.y) + (v6.z + v6.w)) + ((v7.x + v7.y) + (v7.z + v7.w)));
    __shared__ float ws[NW];
    #pragma unroll
    for (int o = 16; o > 0; o >>= 1) s += __shfl_down_sync(0xffffffffu, s, o);
    if ((threadIdx.x & 31) == 0) ws[threadIdx.x >> 5] = s;
    __syncthreads();
    if (threadIdx.x < 32) {
        float t = (threadIdx.x < NW) ? ws[threadIdx.x] : 0.f;
        #pragma unroll
        for (int o = 4; o > 0; o >>= 1) t += __shfl_down_sync(0xffffffffu, t, o);
        if (threadIdx.x == 0) g_centrality[row] = t / (float)M;
    }
}

// ---------------------------------------------------------------------------
// Kernel 1b: global top-34 / bottom-34 of centrality (one CTA, one-off).
// ---------------------------------------------------------------------------
__global__ __launch_bounds__(TPB) void cextremes_kernel()
{
    __shared__ float    c[BMAX];
    __shared__ unsigned hist[NBINS];
    __shared__ float    tv[CECAP]; __shared__ int ti[CECAP];
    __shared__ float    bv[CECAP]; __shared__ int bi[CECAP];
    __shared__ float    wmn[NW], wmx[NW];
    __shared__ unsigned cntT, cntB;
    __shared__ int      sh_btop, sh_bbot;
    __shared__ float    sh_lo, sh_scale;

    const int tid = threadIdx.x, lane = tid & 31, wid = tid >> 5;
    float mn = FLT_MAX, mx = -FLT_MAX;
    #pragma unroll
    for (int k = 0; k < BMAX / TPB; k++) {
        float v = g_centrality[tid + k * TPB];
        c[tid + k * TPB] = v;
        mn = fminf(mn, v); mx = fmaxf(mx, v);
    }
    if (tid < NBINS) hist[tid] = 0u;
    if (tid == 0) { cntT = 0u; cntB = 0u; }
    #pragma unroll
    for (int o = 16; o > 0; o >>= 1) {
        mn = fminf(mn, __shfl_xor_sync(0xffffffffu, mn, o));
        mx = fmaxf(mx, __shfl_xor_sync(0xffffffffu, mx, o));
    }
    if (lane == 0) { wmn[wid] = mn; wmx[wid] = mx; }
    __syncthreads();
    if (tid == 0) {
        float lo = wmn[0], hi = wmx[0];
        #pragma unroll
        for (int w = 1; w < NW; w++) { lo = fminf(lo, wmn[w]); hi = fmaxf(hi, wmx[w]); }
        sh_lo = lo;
        sh_scale = (float)NBINS / fmaxf(hi - lo, 1e-30f);
    }
    __syncthreads();
    const float lo = sh_lo, scale = sh_scale;
    #pragma unroll
    for (int k = 0; k < BMAX / TPB; k++) {
        int b = (int)((c[tid + k * TPB] - lo) * scale);
        b = min(max(b, 0), NBINS - 1);
        atomicAdd(&hist[b], 1u);
    }
    __syncthreads();
    if (tid == 0) {              // serial bin scans (256 bins, one-off kernel)
        unsigned cum = 0u; int b = NBINS - 1;
        for (; b >= 0; b--) { cum += hist[b]; if (cum >= NEXT) break; }
        sh_btop = b;
        cum = 0u; b = 0;
        for (; b < NBINS; b++) { cum += hist[b]; if (cum >= NEXT) break; }
        sh_bbot = b;
    }
    __syncthreads();
    const int btop = sh_btop, bbot = sh_bbot;
    #pragma unroll
    for (int k = 0; k < BMAX / TPB; k++) {
        int idx = tid + k * TPB;
        float v = c[idx];
        int b = (int)((v - lo) * scale);
        b = min(max(b, 0), NBINS - 1);
        if (b >= btop) { unsigned p = atomicAdd(&cntT, 1u); if (p < CECAP) { tv[p] = v; ti[p] = idx; } }
        if (b <= bbot) { unsigned p = atomicAdd(&cntB, 1u); if (p < CECAP) { bv[p] = v; bi[p] = idx; } }
    }
    __syncthreads();
    {
        int n = (int)min(cntT, (unsigned)CECAP);
        for (int q = tid; q < n; q += TPB) {
            float v = tv[q]; int id = ti[q]; int r = 0;
            for (int d = 0; d < n; d++) {
                float vd = tv[d];
                r += (vd > v) || (vd == v && ti[d] < id);
            }
            if (r < NEXT) { g_topv[r] = v; g_topi[r] = id; }
        }
        n = (int)min(cntB, (unsigned)CECAP);
        for (int q = tid; q < n; q += TPB) {
            float v = bv[q]; int id = bi[q]; int r = 0;
            for (int d = 0; d < n; d++) {
                float vd = bv[d];
                r += (vd < v) || (vd == v && bi[d] < id);
            }
            if (r < NEXT) { g_botv[r] = v; g_boti[r] = id; }
        }
    }
}

// ---------------------------------------------------------------------------
// Kernel 2: per-row loss. Thread-max prefilter select (256 atomics, 2 passes).
// ---------------------------------------------------------------------------
__global__ __launch_bounds__(TPB) void rowloss_kernel(
    const float* __restrict__ sim, const float* __restrict__ temp_p, int B)
{
    __shared__ float    srow[BMAX];
    __shared__ unsigned hist[NBINS];
    __shared__ float    cand_val[CAP];
    __shared__ int      cand_idx[CAP];
    __shared__ float    topval[KNB];
    __shared__ int      topidx[KNB];
    __shared__ int      exclidx[KNB + 1];
    __shared__ float    stv[NEXT]; __shared__ int sti[NEXT];
    __shared__ float    sbv[NEXT]; __shared__ int sbi[NEXT];
    __shared__ float    wmn[NW], wmx[NW];
    __shared__ unsigned sh_cnt;
    __shared__ int      sh_bstar;
    __shared__ float    sh_lo, sh_scale, sh_diag, sh_mxs;

    const int i    = blockIdx.x;
    const int tid  = threadIdx.x;
    const int wid  = tid >> 5;
    const int lane = tid & 31;

    // ---- load row, per-thread min/max/threadmax (diag excluded); stage
    //      centrality extreme tables into smem; zero aux ----
    float mn = FLT_MAX, mx = -FLT_MAX, tm = -FLT_MAX;
    {
        const float4* rp = (const float4*)(sim + (size_t)i * B);
        const int dq = i >> 2, dl = i & 3;
        #pragma unroll
        for (int k = 0; k < 4; k++) {
            int j = tid + k * TPB;
            float4 v = rp[j];
            ((float4*)srow)[j] = v;
            float a = v.x, b = v.y, c = v.z, d = v.w;
            if (j == dq) {
                float dv = (dl == 0) ? a : (dl == 1) ? b : (dl == 2) ? c : d;
                sh_diag = dv;
                const float rep = (dl == 0) ? b : a;
                if (dl == 0) a = rep; else if (dl == 1) b = rep;
                else if (dl == 2) c = rep; else d = rep;
            }
            float lmx = fmaxf(fmaxf(a, b), fmaxf(c, d));
            mn = fminf(mn, fminf(fminf(a, b), fminf(c, d)));
            mx = fmaxf(mx, lmx);
            tm = fmaxf(tm, lmx);
        }
        if (tid < NBINS) hist[tid] = 0u;
        if (tid < NEXT) { stv[tid] = g_topv[tid]; sti[tid] = g_topi[tid];
                          sbv[tid] = g_botv[tid]; sbi[tid] = g_boti[tid]; }
        if (tid == 0) { sh_cnt = 0u; exclidx[KNB] = i; }
    }
    #pragma unroll
    for (int o = 16; o > 0; o >>= 1) {
        mn = fminf(mn, __shfl_xor_sync(0xffffffffu, mn, o));
        mx = fmaxf(mx, __shfl_xor_sync(0xffffffffu, mx, o));
    }
    if (lane == 0) { wmn[wid] = mn; wmx[wid] = mx; }
    __syncthreads();
    if (tid == 0) {
        float lo = wmn[0], hi = wmx[0];
        #pragma unroll
        for (int w = 1; w < NW; w++) { lo = fminf(lo, wmn[w]); hi = fmaxf(hi, wmx[w]); }
        sh_lo = lo;
        sh_scale = (float)NBINS / fmaxf(hi - lo, 1e-30f);
    }
    __syncthreads();

    const float lo = sh_lo, scale = sh_scale;

    // ---- histogram the 256 per-thread maxima (one atomic per thread) ----
    {
        int b = (int)((tm - lo) * scale);
        b = min(max(b, 0), NBINS - 1);
        atomicAdd(&hist[b], 1u);
    }
    __syncthreads();

    // ---- b* = bin of the 33rd-largest thread-max (warp-0 suffix scan).
    //      Every v with bin >= b* is a candidate; provably covers top-33. ----
    if (wid == 0) {
        unsigned running = 0u;
        int bstar = 0;
        bool found = false;
        for (int c = 0; c < NBINS / 32 && !found; c++) {
            int bin = NBINS - 1 - c * 32 - lane;
            unsigned p = hist[bin];
            #pragma unroll
            for (int o = 1; o < 32; o <<= 1) {
                unsigned t = __shfl_up_sync(0xffffffffu, p, o);
                if (lane >= o) p += t;
            }
            unsigned cum = running + p;
            unsigned ball = __ballot_sync(0xffffffffu, cum >= 33u);
            running += __shfl_sync(0xffffffffu, p, 31);
            if (ball) { bstar = NBINS - 1 - c * 32 - (__ffs(ball) - 1); found = true; }
        }
        if (lane == 0) sh_bstar = bstar;
    }
    __syncthreads();

    // ---- collect candidates with bin >= b* ----
    {
        const int bstar = sh_bstar;
        #pragma unroll
        for (int k = 0; k < 4; k++) {
            int j = tid + k * TPB;
            float4 v = ((const float4*)srow)[j];
            int base = j << 2;
            #pragma unroll
            for (int e = 0; e < 4; e++) {
                float f = (e == 0) ? v.x : (e == 1) ? v.y : (e == 2) ? v.z : v.w;
                int idx = base + e;
                int b = (int)((f - lo) * scale);
                b = min(max(b, 0), NBINS - 1);
                if (b >= bstar && idx != i) {
                    unsigned pos = atomicAdd(&sh_cnt, 1u);
                    if (pos < CAP) { cand_val[pos] = f; cand_idx[pos] = idx; }
                }
            }
        }
    }
    __syncthreads();

    // ---- exact rank by counting (ties: lower index first, matches top_k) ----
    {
        int n = (int)min(sh_cnt, (unsigned)CAP);
        for (int c = tid; c < n; c += TPB) {
            float v = cand_val[c];
            int   id = cand_idx[c];
            int r = 0;
            for (int d = 0; d < n; d++) {
                float vd = cand_val[d];
                r += (vd > v) || (vd == v && cand_idx[d] < id);
            }
            if (r < KNB) {
                topval[r] = v;
                topidx[r] = id;
                exclidx[r] = id;
            } else if (r == KNB) {
                sh_mxs = v;                        // mx_s = 33rd largest off-diag
            }
        }
    }
    __syncthreads();

    // ---- warp 0: centrality extremes over non-excluded via global 34-lists,
    //      then the epilogue ----
    if (tid < 32) {
        const int ex = (lane <= KNB) ? exclidx[lane] : -1;   // 33 excluded ids
        float mx_c = stv[NEXT - 1];
        #pragma unroll 4
        for (int e = 0; e < NEXT; e++) {
            int id = sti[e];
            if (!__ballot_sync(0xffffffffu, ex == id)) { mx_c = stv[e]; break; }
        }
        float mn_c = sbv[NEXT - 1];
        #pragma unroll 4
        for (int e = 0; e < NEXT; e++) {
            int id = sbi[e];
            if (!__ballot_sync(0xffffffffu, ex == id)) { mn_c = sbv[e]; break; }
        }
        const float mn_s = sh_lo, mx_s = sh_mxs;

        float tv2 = topval[lane];
        int   ti2 = topidx[lane];
        float dg  = sh_diag;

        // logsumexp over extended set (32 neighbors + diagonal)
        float m = tv2;
        #pragma unroll
        for (int o = 16; o > 0; o >>= 1) m = fmaxf(m, __shfl_xor_sync(0xffffffffu, m, o));
        m = fmaxf(m, dg);
        float s = expf(tv2 - m);
        #pragma unroll
        for (int o = 16; o > 0; o >>= 1) s += __shfl_xor_sync(0xffffffffu, s, o);
        s += expf(dg - m);
        float lse = logf(s) + m;

        // positive weights: softmax over neighbors of (norm_sim - norm_cent)*T
        float T  = *temp_p;
        float ns = (tv2 - mn_s) / (mx_s - mn_s);
        float nc = (g_centrality[ti2] - mn_c) / (mx_c - mn_c);
        float a  = (ns - nc) * T;
        float am = a;
        #pragma unroll
        for (int o = 16; o > 0; o >>= 1) am = fmaxf(am, __shfl_xor_sync(0xffffffffu, am, o));
        float pe = expf(a - am);
        float ps = pe;
        #pragma unroll
        for (int o = 16; o > 0; o >>= 1) ps += __shfl_xor_sync(0xffffffffu, ps, o);
        float pw = pe / ps;

        float num   = pw * (tv2 - lse);
        float pwsum = pw;
        #pragma unroll
        for (int o = 16; o > 0; o >>= 1) {
            num   += __shfl_xor_sync(0xffffffffu, num,   o);
            pwsum += __shfl_xor_sync(0xffffffffu, pwsum, o);
        }
        if (lane == 0) {
            float numer = num + (dg - lse);
            float denom = pwsum + 1.0f;
            g_rowloss[i] = -numer / denom;
        }
    }
}

// ---------------------------------------------------------------------------
// Kernel 3: deterministic mean over rows
// ---------------------------------------------------------------------------
__global__ __launch_bounds__(TPB) void reduce_kernel(float* __restrict__ out, int B)
{
    double s = 0.0;
    for (int j = threadIdx.x; j < B; j += TPB) s += (double)g_rowloss[j];
    __shared__ double ws[NW];
    #pragma unroll
    for (int o = 16; o > 0; o >>= 1) s += __shfl_down_sync(0xffffffffu, s, o);
    if ((threadIdx.x & 31) == 0) ws[threadIdx.x >> 5] = s;
    __syncthreads();
    if (threadIdx.x < 32) {
        double t = (threadIdx.x < NW) ? ws[threadIdx.x] : 0.0;
        #pragma unroll
        for (int o = 4; o > 0; o >>= 1) t += __shfl_down_sync(0xffffffffu, t, o);
        if (threadIdx.x == 0) out[0] = (float)(t / (double)B);
    }
}

// ---------------------------------------------------------------------------
extern "C" void kernel_launch(void* const* d_in, const int* in_sizes, int n_in,
                              void* d_out, int out_size)
{
    const float* sim  = (const float*)d_in[0];
    const float* mem  = (const float*)d_in[1];
    const float* temp = (const float*)d_in[n_in - 1];

    int nsim = in_sizes[0];
    int B = 1;
    while ((long long)B * B < (long long)nsim) B <<= 1;   // B = 4096
    int M = in_sizes[1] / B;                               // M = 8192

    centrality_kernel<<<B, TPB>>>(mem, B, M);
    cextremes_kernel<<<1, TPB>>>();
    rowloss_kernel<<<B, TPB>>>(sim, temp, B);
    reduce_kernel<<<1, TPB>>>((float*)d_out, B);
}